// round 7
// baseline (speedup 1.0000x reference)
#include <cuda_runtime.h>
#include <math.h>
#include <stdint.h>

#define DT 0.01f
#define TWO_PI 6.28318530717958647692f

#define BSZ 4096
#define DSZ 2048
#define NSZ 4096

// scan chunking
#define CCH 128
#define LCH (BSZ / CCH)   // 32

// int8 quantization: val = STEP * (128*h + l),  |128h + l| <= 16256
#define SXQ (6.5f / 16384.0f)
#define SWQ (0.145f / 16384.0f)
#define INV_SXQ (16384.0f / 6.5f)
#define INV_SWQ (16384.0f / 0.145f)
#define FS_HH (SXQ * SWQ * 16384.0f)
#define FS_MIX (SXQ * SWQ * 128.0f)

// GEMM tiling
#define GBM 128
#define GBN 128
#define GBK 32                     // s8 elems (bytes) per k-stage
#define ROWB 48                    // padded smem row bytes (32B data + 16B pad)
#define PLANEB (128 * ROWB)        // 6144
#define STAGEB (4 * PLANEB)        // Xh, Xl, Wh, Wl
#define NSTG 3
#define KITERS (DSZ / GBK)         // 64
#define SMEM_BYTES (NSTG * STAGEB) // 73728

// ---------------- static device scratch (no allocations allowed) -----------
__device__ int8_t g_Xh[(size_t)BSZ * DSZ];
__device__ int8_t g_Xl[(size_t)BSZ * DSZ];
__device__ int8_t g_Wh[(size_t)NSZ * DSZ];
__device__ int8_t g_Wl[(size_t)NSZ * DSZ];
__device__ float g_force[(size_t)BSZ * NSZ];
__device__ float g_cs[CCH * NSZ], g_cv[CCH * NSZ];
__device__ float g_zs[CCH * NSZ], g_zv[CCH * NSZ];

// ---------------- helpers --------------------------------------------------
__device__ __forceinline__ uint32_t smem_u32(const void* p) {
    uint32_t a;
    asm("{ .reg .u64 t; cvta.to.shared.u64 t, %1; cvt.u32.u64 %0, t; }" : "=r"(a) : "l"(p));
    return a;
}
__device__ __forceinline__ void cp16(uint32_t dst, const void* src) {
    asm volatile("cp.async.cg.shared.global [%0], [%1], 16;\n" :: "r"(dst), "l"(src));
}
__device__ __forceinline__ void ldsm_x4(uint32_t* r, uint32_t addr) {
    asm volatile("ldmatrix.sync.aligned.m8n8.x4.shared.b16 {%0,%1,%2,%3}, [%4];"
                 : "=r"(r[0]), "=r"(r[1]), "=r"(r[2]), "=r"(r[3]) : "r"(addr));
}
__device__ __forceinline__ void imma(int* d, const uint32_t* a, uint32_t b0, uint32_t b1) {
    asm volatile(
        "mma.sync.aligned.m16n8k32.row.col.s32.s8.s8.s32 "
        "{%0,%1,%2,%3}, {%4,%5,%6,%7}, {%8,%9}, {%0,%1,%2,%3};"
        : "+r"(d[0]), "+r"(d[1]), "+r"(d[2]), "+r"(d[3])
        : "r"(a[0]), "r"(a[1]), "r"(a[2]), "r"(a[3]), "r"(b0), "r"(b1));
}

// ---------------- quantize fp32 -> 2-limb int8 -----------------------------
__device__ __forceinline__ void quant1(float x, float inv_step, int8_t& h, int8_t& l) {
    float qf = x * inv_step;
    qf = fminf(16256.0f, fmaxf(-16256.0f, qf));
    float hf = rintf(qf * 0.0078125f);            // /128
    float lf = rintf(qf - hf * 128.0f);
    h = (int8_t)(int)hf;
    l = (int8_t)(int)lf;
}
__global__ __launch_bounds__(256) void quant_kernel(const float* __restrict__ src,
                                                    int8_t* __restrict__ hp,
                                                    int8_t* __restrict__ lp,
                                                    float inv_step) {
    size_t i = (size_t)blockIdx.x * 256 + threadIdx.x;   // float4 index
    float4 a = reinterpret_cast<const float4*>(src)[i];
    int8_t hx, lx, hy, ly, hz, lz, hw, lw;
    quant1(a.x, inv_step, hx, lx);
    quant1(a.y, inv_step, hy, ly);
    quant1(a.z, inv_step, hz, lz);
    quant1(a.w, inv_step, hw, lw);
    reinterpret_cast<char4*>(hp)[i] = make_char4(hx, hy, hz, hw);
    reinterpret_cast<char4*>(lp)[i] = make_char4(lx, ly, lz, lw);
}

// ---------------- int8 2-limb GEMM: force = x @ W^T + b --------------------
__global__ __launch_bounds__(256, 1) void gemm_i8_kernel(const float* __restrict__ bias) {
    extern __shared__ char smem_raw[];
    const uint32_t sbase = smem_u32(smem_raw);
    const int tid = threadIdx.x;
    const int lane = tid & 31;
    const int wid = tid >> 5;
    const int m0 = blockIdx.y * GBM;
    const int n0 = blockIdx.x * GBN;
    const int wm = (wid >> 2) * 64;   // warp tile 64 (M) x 32 (N)
    const int wn = (wid & 3) * 32;

    int hh[4][4][4], mx[4][4][4];
    #pragma unroll
    for (int mt = 0; mt < 4; ++mt)
        #pragma unroll
        for (int nt = 0; nt < 4; ++nt)
            #pragma unroll
            for (int r = 0; r < 4; ++r) { hh[mt][nt][r] = 0; mx[mt][nt][r] = 0; }

    const uint32_t ld_row = (uint32_t)(lane & 15);
    const uint32_t ld_col = (uint32_t)((lane >> 4) & 1) * 16;

    // per-thread stage-load addressing: 128 rows x 2 chunks per plane
    const int srow = tid >> 1;
    const uint32_t sc16 = (uint32_t)(tid & 1) * 16;
    const uint32_t soff = (uint32_t)srow * ROWB + sc16;

    auto load_stage = [&](int s, int buf) {
        uint32_t sb = sbase + (uint32_t)buf * STAGEB;
        size_t ko = (size_t)s * GBK + sc16;
        size_t gX = (size_t)(m0 + srow) * DSZ + ko;
        size_t gW = (size_t)(n0 + srow) * DSZ + ko;
        cp16(sb + soff, g_Xh + gX);
        cp16(sb + PLANEB + soff, g_Xl + gX);
        cp16(sb + 2 * PLANEB + soff, g_Wh + gW);
        cp16(sb + 3 * PLANEB + soff, g_Wl + gW);
    };

    // prologue
    load_stage(0, 0);
    asm volatile("cp.async.commit_group;\n" ::: "memory");
    load_stage(1, 1);
    asm volatile("cp.async.commit_group;\n" ::: "memory");
    asm volatile("cp.async.wait_group 1;\n" ::: "memory");
    __syncthreads();

    for (int s = 0; s < KITERS; ++s) {
        if (s + 2 < KITERS) {
            load_stage(s + 2, (s + 2) % NSTG);
            asm volatile("cp.async.commit_group;\n" ::: "memory");
        }
        const uint32_t sb = sbase + (uint32_t)(s % NSTG) * STAGEB;

        uint32_t ah[4][4], al[4][4], bh[2][4], bl[2][4];
        #pragma unroll
        for (int mt = 0; mt < 4; ++mt) {
            uint32_t addr = sb + (uint32_t)(wm + mt * 16 + (int)ld_row) * ROWB + ld_col;
            ldsm_x4(ah[mt], addr);
            ldsm_x4(al[mt], addr + PLANEB);
        }
        #pragma unroll
        for (int p = 0; p < 2; ++p) {
            uint32_t addr = sb + 2 * PLANEB +
                            (uint32_t)(wn + p * 16 + (int)ld_row) * ROWB + ld_col;
            ldsm_x4(bh[p], addr);
            ldsm_x4(bl[p], addr + PLANEB);
        }

        #pragma unroll
        for (int mt = 0; mt < 4; ++mt)
            #pragma unroll
            for (int p = 0; p < 2; ++p)
                #pragma unroll
                for (int h = 0; h < 2; ++h) {
                    const int nt = p * 2 + h;
                    imma(hh[mt][nt], ah[mt], bh[p][h], bh[p][2 + h]);
                    imma(mx[mt][nt], ah[mt], bl[p][h], bl[p][2 + h]);
                    imma(mx[mt][nt], al[mt], bh[p][h], bh[p][2 + h]);
                }

        if (s + 1 < KITERS) {
            if (s + 2 < KITERS)
                asm volatile("cp.async.wait_group 1;\n" ::: "memory");
            else
                asm volatile("cp.async.wait_group 0;\n" ::: "memory");
            __syncthreads();
        }
    }

    // ---- epilogue: rescale, add bias, write force ----
    #pragma unroll
    for (int nt = 0; nt < 4; ++nt) {
        int c = n0 + wn + nt * 8 + (lane & 3) * 2;
        float b0 = __ldg(&bias[c]);
        float b1 = __ldg(&bias[c + 1]);
        #pragma unroll
        for (int mt = 0; mt < 4; ++mt) {
            int r = m0 + wm + mt * 16 + (lane >> 2);
            float2 lo, hi;
            lo.x = fmaf(FS_HH, (float)hh[mt][nt][0], fmaf(FS_MIX, (float)mx[mt][nt][0], b0));
            lo.y = fmaf(FS_HH, (float)hh[mt][nt][1], fmaf(FS_MIX, (float)mx[mt][nt][1], b1));
            hi.x = fmaf(FS_HH, (float)hh[mt][nt][2], fmaf(FS_MIX, (float)mx[mt][nt][2], b0));
            hi.y = fmaf(FS_HH, (float)hh[mt][nt][3], fmaf(FS_MIX, (float)mx[mt][nt][3], b1));
            *reinterpret_cast<float2*>(&g_force[(size_t)r * NSZ + c]) = lo;
            *reinterpret_cast<float2*>(&g_force[(size_t)(r + 8) * NSZ + c]) = hi;
        }
    }
}

// ---------------- scan phase A: per-chunk carries (zero init) -------------
__global__ __launch_bounds__(256) void scanA_kernel(const float* __restrict__ freq,
                                                    const float* __restrict__ damp) {
    int c4 = blockIdx.x * 256 + threadIdx.x;
    int j = blockIdx.y;
    int n = c4 * 4;
    float4 f4 = *reinterpret_cast<const float4*>(freq + n);
    float4 d4 = *reinterpret_cast<const float4*>(damp + n);
    float wx = (TWO_PI * f4.x) * (TWO_PI * f4.x);
    float wy = (TWO_PI * f4.y) * (TWO_PI * f4.y);
    float wz = (TWO_PI * f4.z) * (TWO_PI * f4.z);
    float ww = (TWO_PI * f4.w) * (TWO_PI * f4.w);
    float sx = 0, sy = 0, sz = 0, sw = 0, vx = 0, vy = 0, vz = 0, vw = 0;
    const float4* fp = reinterpret_cast<const float4*>(g_force + (size_t)j * LCH * NSZ + n);
    #pragma unroll 8
    for (int k = 0; k < LCH; ++k) {
        float4 fr = fp[(size_t)k * (NSZ / 4)];
        float ax = fmaf(-wx, sx, fmaf(-d4.x, vx, fr.x)); vx = fmaf(ax, DT, vx); sx = fmaf(vx, DT, sx);
        float ay = fmaf(-wy, sy, fmaf(-d4.y, vy, fr.y)); vy = fmaf(ay, DT, vy); sy = fmaf(vy, DT, sy);
        float az = fmaf(-wz, sz, fmaf(-d4.z, vz, fr.z)); vz = fmaf(az, DT, vz); sz = fmaf(vz, DT, sz);
        float aw = fmaf(-ww, sw, fmaf(-d4.w, vw, fr.w)); vw = fmaf(aw, DT, vw); sw = fmaf(vw, DT, sw);
    }
    *reinterpret_cast<float4*>(g_cs + (size_t)j * NSZ + n) = make_float4(sx, sy, sz, sw);
    *reinterpret_cast<float4*>(g_cv + (size_t)j * NSZ + n) = make_float4(vx, vy, vz, vw);
}

// ---------------- combine: z_{j+1} = M^L z_j + carry_j --------------------
__global__ __launch_bounds__(256) void combine_kernel(const float* __restrict__ freq,
                                                      const float* __restrict__ damp) {
    int n = blockIdx.x * 256 + threadIdx.x;
    float f = freq[n], dmp = damp[n];
    float w2 = (TWO_PI * f) * (TWO_PI * f);
    float b00 = 1.0f - w2 * DT * DT;
    float b01 = DT * (1.0f - dmp * DT);
    float b10 = -w2 * DT;
    float b11 = 1.0f - dmp * DT;
    float e00 = 1.0f, e01 = 0.0f, e10 = 0.0f, e11 = 1.0f;
    int p = LCH;
    while (p) {
        if (p & 1) {
            float t00 = b00 * e00 + b01 * e10, t01 = b00 * e01 + b01 * e11;
            float t10 = b10 * e00 + b11 * e10, t11 = b10 * e01 + b11 * e11;
            e00 = t00; e01 = t01; e10 = t10; e11 = t11;
        }
        float s00 = b00 * b00 + b01 * b10, s01 = b00 * b01 + b01 * b11;
        float s10 = b10 * b00 + b11 * b10, s11 = b10 * b01 + b11 * b11;
        b00 = s00; b01 = s01; b10 = s10; b11 = s11;
        p >>= 1;
    }
    float sz = 0.0f, vz = 0.0f;
    for (int j = 0; j < CCH; ++j) {
        g_zs[j * NSZ + n] = sz;
        g_zv[j * NSZ + n] = vz;
        float cs = g_cs[j * NSZ + n], cv = g_cv[j * NSZ + n];
        float ns = e00 * sz + e01 * vz + cs;
        float nv = e10 * sz + e11 * vz + cv;
        sz = ns; vz = nv;
    }
}

// ---------------- scan phase B: full scan from z, + osc, clip, write ------
__global__ __launch_bounds__(256) void scanB_kernel(const float* __restrict__ freq,
                                                    const float* __restrict__ damp,
                                                    const float* __restrict__ amp,
                                                    const float* __restrict__ phase,
                                                    float* __restrict__ out) {
    int c4 = blockIdx.x * 256 + threadIdx.x;
    int j = blockIdx.y;
    int n = c4 * 4;
    float4 f4 = *reinterpret_cast<const float4*>(freq + n);
    float4 d4 = *reinterpret_cast<const float4*>(damp + n);
    float4 a4 = *reinterpret_cast<const float4*>(amp + n);
    float4 p4 = *reinterpret_cast<const float4*>(phase + n);
    float wx = (TWO_PI * f4.x) * (TWO_PI * f4.x);
    float wy = (TWO_PI * f4.y) * (TWO_PI * f4.y);
    float wz = (TWO_PI * f4.z) * (TWO_PI * f4.z);
    float ww = (TWO_PI * f4.w) * (TWO_PI * f4.w);
    float ox = a4.x * sinf(fmaf(TWO_PI * f4.x, DT, p4.x));
    float oy = a4.y * sinf(fmaf(TWO_PI * f4.y, DT, p4.y));
    float oz = a4.z * sinf(fmaf(TWO_PI * f4.z, DT, p4.z));
    float ow = a4.w * sinf(fmaf(TWO_PI * f4.w, DT, p4.w));
    float4 zs = *reinterpret_cast<const float4*>(g_zs + (size_t)j * NSZ + n);
    float4 zv = *reinterpret_cast<const float4*>(g_zv + (size_t)j * NSZ + n);
    float sx = zs.x, sy = zs.y, szz = zs.z, sww = zs.w;
    float vx = zv.x, vy = zv.y, vzz = zv.z, vww = zv.w;
    const float4* fp = reinterpret_cast<const float4*>(g_force + (size_t)j * LCH * NSZ + n);
    float4* op = reinterpret_cast<float4*>(out + (size_t)j * LCH * NSZ + n);
    #pragma unroll 8
    for (int k = 0; k < LCH; ++k) {
        float4 fr = fp[(size_t)k * (NSZ / 4)];
        float ax = fmaf(-wx, sx, fmaf(-d4.x, vx, fr.x)); vx = fmaf(ax, DT, vx); sx = fmaf(vx, DT, sx);
        float ay = fmaf(-wy, sy, fmaf(-d4.y, vy, fr.y)); vy = fmaf(ay, DT, vy); sy = fmaf(vy, DT, sy);
        float az = fmaf(-wz, szz, fmaf(-d4.z, vzz, fr.z)); vzz = fmaf(az, DT, vzz); szz = fmaf(vzz, DT, szz);
        float aw = fmaf(-ww, sww, fmaf(-d4.w, vww, fr.w)); vww = fmaf(aw, DT, vww); sww = fmaf(vww, DT, sww);
        float4 o;
        o.x = fminf(1.0f, fmaxf(-1.0f, sx + ox));
        o.y = fminf(1.0f, fmaxf(-1.0f, sy + oy));
        o.z = fminf(1.0f, fmaxf(-1.0f, szz + oz));
        o.w = fminf(1.0f, fmaxf(-1.0f, sww + ow));
        op[(size_t)k * (NSZ / 4)] = o;
    }
}

// ---------------------------------------------------------------------------
extern "C" void kernel_launch(void* const* d_in, const int* in_sizes, int n_in,
                              void* d_out, int out_size)
{
    const float* x     = (const float*)d_in[0];
    const float* W     = (const float*)d_in[1];
    const float* b     = (const float*)d_in[2];
    const float* amp   = (const float*)d_in[3];
    const float* freq  = (const float*)d_in[4];
    const float* phase = (const float*)d_in[5];
    const float* damp  = (const float*)d_in[6];
    float* out = (float*)d_out;
    (void)in_sizes; (void)n_in; (void)out_size;

    static bool attr_done = false;
    if (!attr_done) {
        cudaFuncSetAttribute(gemm_i8_kernel,
                             cudaFuncAttributeMaxDynamicSharedMemorySize, SMEM_BYTES);
        attr_done = true;
    }

    // 1. quantize operands into 2-limb int8 planes
    int8_t *xh, *xl, *wh, *wl;
    cudaGetSymbolAddress((void**)&xh, g_Xh);
    cudaGetSymbolAddress((void**)&xl, g_Xl);
    cudaGetSymbolAddress((void**)&wh, g_Wh);
    cudaGetSymbolAddress((void**)&wl, g_Wl);
    quant_kernel<<<(BSZ * DSZ / 4) / 256, 256>>>(x, xh, xl, INV_SXQ);
    quant_kernel<<<(NSZ * DSZ / 4) / 256, 256>>>(W, wh, wl, INV_SWQ);

    // 2. int8 2-limb tensor-core GEMM -> g_force (bias fused in epilogue)
    dim3 ggrid(NSZ / GBN, BSZ / GBM);
    gemm_i8_kernel<<<ggrid, 256, SMEM_BYTES>>>(b);

    // 3. chunked parallel scan
    dim3 sgrid(NSZ / 4 / 256, CCH);
    scanA_kernel<<<sgrid, 256>>>(freq, damp);
    combine_kernel<<<NSZ / 256, 256>>>(freq, damp);
    scanB_kernel<<<sgrid, 256>>>(freq, damp, amp, phase, out);
}

// round 10
// speedup vs baseline: 4.9004x; 4.9004x over previous
#include <cuda_runtime.h>
#include <cuda_fp16.h>
#include <math.h>
#include <stdint.h>

#define DT 0.01f
#define TWO_PI 6.28318530717958647692f

#define BSZ 4096
#define DSZ 2048
#define NSZ 4096

// scan chunking
#define CCH 128
#define LCH (BSZ / CCH)   // 32

// GEMM tiling
#define GBM 128
#define GBN 128
#define GBK 32                    // fp16 elems per stage (two k16 micro-steps)
#define ROWB 80                   // padded smem row bytes (64B data + 16B pad)
#define TILEB (128 * ROWB)        // 10240 bytes per matrix tile
#define STAGEB (2 * TILEB)        // A, B
#define NSTG 3
#define KITERS (DSZ / GBK)        // 64
#define SMEM_BYTES (NSTG * STAGEB) // 61440

// ---------------- static device scratch (no allocations allowed) -----------
__device__ __half g_Ah[(size_t)BSZ * DSZ];
__device__ __half g_Wh[(size_t)NSZ * DSZ];
__device__ float g_force[(size_t)BSZ * NSZ];
__device__ float g_cs[CCH * NSZ], g_cv[CCH * NSZ];
__device__ float g_zs[CCH * NSZ], g_zv[CCH * NSZ];

// ---------------- helpers --------------------------------------------------
__device__ __forceinline__ uint32_t smem_u32(const void* p) {
    uint32_t a;
    asm("{ .reg .u64 t; cvta.to.shared.u64 t, %1; cvt.u32.u64 %0, t; }" : "=r"(a) : "l"(p));
    return a;
}
__device__ __forceinline__ void cp16(uint32_t dst, const void* src) {
    asm volatile("cp.async.cg.shared.global [%0], [%1], 16;\n" :: "r"(dst), "l"(src));
}
__device__ __forceinline__ void ldsm_x4(uint32_t* r, uint32_t addr) {
    asm volatile("ldmatrix.sync.aligned.m8n8.x4.shared.b16 {%0,%1,%2,%3}, [%4];"
                 : "=r"(r[0]), "=r"(r[1]), "=r"(r[2]), "=r"(r[3]) : "r"(addr));
}
__device__ __forceinline__ void mma_f16(float* d, const uint32_t* a, const uint32_t* b) {
    asm volatile(
        "mma.sync.aligned.m16n8k16.row.col.f32.f16.f16.f32 "
        "{%0,%1,%2,%3}, {%4,%5,%6,%7}, {%8,%9}, {%0,%1,%2,%3};"
        : "+f"(d[0]), "+f"(d[1]), "+f"(d[2]), "+f"(d[3])
        : "r"(a[0]), "r"(a[1]), "r"(a[2]), "r"(a[3]), "r"(b[0]), "r"(b[1]));
}

// ---------------- convert kernels: fp32 -> fp16 ----------------------------
__global__ __launch_bounds__(256) void cvtA_kernel(const float* __restrict__ src) {
    size_t i = (size_t)blockIdx.x * 256 + threadIdx.x;
    float4 a = reinterpret_cast<const float4*>(src)[i];
    __half2 lo = __floats2half2_rn(a.x, a.y);
    __half2 hi = __floats2half2_rn(a.z, a.w);
    uint2 o;
    o.x = *reinterpret_cast<uint32_t*>(&lo);
    o.y = *reinterpret_cast<uint32_t*>(&hi);
    reinterpret_cast<uint2*>(g_Ah)[i] = o;
}
__global__ __launch_bounds__(256) void cvtW_kernel(const float* __restrict__ src) {
    size_t i = (size_t)blockIdx.x * 256 + threadIdx.x;
    float4 a = reinterpret_cast<const float4*>(src)[i];
    __half2 lo = __floats2half2_rn(a.x, a.y);
    __half2 hi = __floats2half2_rn(a.z, a.w);
    uint2 o;
    o.x = *reinterpret_cast<uint32_t*>(&lo);
    o.y = *reinterpret_cast<uint32_t*>(&hi);
    reinterpret_cast<uint2*>(g_Wh)[i] = o;
}

// ---------------- fp16 mma.sync GEMM: force = x @ W^T + b -----------------
struct Frag {
    uint32_t a[4][4];
    uint32_t b[2][4];
};

__global__ __launch_bounds__(256, 1) void gemm_f16_kernel(const float* __restrict__ bias) {
    extern __shared__ char smem_raw[];
    const uint32_t sbase = smem_u32(smem_raw);
    const int tid = threadIdx.x;
    const int lane = tid & 31;
    const int wid = tid >> 5;
    const int m0 = blockIdx.y * GBM;
    const int n0 = blockIdx.x * GBN;
    const int wm = (wid >> 2) * 64;   // 2 warp rows
    const int wn = (wid & 3) * 32;    // 4 warp cols

    float acc[4][4][4];
    #pragma unroll
    for (int mt = 0; mt < 4; ++mt)
        #pragma unroll
        for (int nt = 0; nt < 4; ++nt)
            #pragma unroll
            for (int r = 0; r < 4; ++r)
                acc[mt][nt][r] = 0.0f;

    const uint32_t a_row_off = (uint32_t)(wm + (lane & 15)) * ROWB;
    const uint32_t a_csel = ((lane >> 4) & 1) * 16;
    const uint32_t b_row_off = (uint32_t)(wn + ((lane >> 4) & 1) * 8 + (lane & 7)) * ROWB;
    const uint32_t b_csel = ((lane >> 3) & 1) * 16;

    auto load_stage = [&](int s, int buf) {
        uint32_t sb = sbase + (uint32_t)buf * STAGEB;
        int k0 = s * GBK;
        #pragma unroll
        for (int it = 0; it < 2; ++it) {
            int c = tid + it * 256;
            int row = c >> 2, c16 = c & 3;
            uint32_t soff = (uint32_t)row * ROWB + (uint32_t)c16 * 16;
            size_t gA = (size_t)(m0 + row) * DSZ + k0 + c16 * 8;
            size_t gB = (size_t)(n0 + row) * DSZ + k0 + c16 * 8;
            cp16(sb + soff, g_Ah + gA);
            cp16(sb + TILEB + soff, g_Wh + gB);
        }
    };

    auto load_frags = [&](Frag& f, uint32_t sb, int ks) {
        const uint32_t acol = (uint32_t)(ks * 32) + a_csel;
        const uint32_t bcol = (uint32_t)(ks * 32) + b_csel;
        #pragma unroll
        for (int mt = 0; mt < 4; ++mt)
            ldsm_x4(f.a[mt], sb + a_row_off + (uint32_t)(mt * 16) * ROWB + acol);
        #pragma unroll
        for (int p = 0; p < 2; ++p)
            ldsm_x4(f.b[p], sb + TILEB + b_row_off + (uint32_t)(p * 16) * ROWB + bcol);
    };

    auto mma_all = [&](const Frag& f) {
        #pragma unroll
        for (int mt = 0; mt < 4; ++mt)
            #pragma unroll
            for (int p = 0; p < 2; ++p)
                #pragma unroll
                for (int h = 0; h < 2; ++h)
                    mma_f16(acc[mt][p * 2 + h], f.a[mt], &f.b[p][h * 2]);
    };

    // prologue: stages 0 and 1 in flight
    load_stage(0, 0);
    asm volatile("cp.async.commit_group;\n" ::: "memory");
    load_stage(1, 1);
    asm volatile("cp.async.commit_group;\n" ::: "memory");
    asm volatile("cp.async.wait_group 1;\n" ::: "memory");
    __syncthreads();

    Frag fa, fb;
    load_frags(fa, sbase, 0);

    for (int s = 0; s < KITERS; ++s) {
        const uint32_t sb_cur = sbase + (uint32_t)(s % NSTG) * STAGEB;
        if (s + 2 < KITERS) {
            load_stage(s + 2, (s + 2) % NSTG);
            asm volatile("cp.async.commit_group;\n" ::: "memory");
        }
        load_frags(fb, sb_cur, 1);
        mma_all(fa);

        if (s + 1 < KITERS) {
            if (s + 2 < KITERS)
                asm volatile("cp.async.wait_group 1;\n" ::: "memory");
            else
                asm volatile("cp.async.wait_group 0;\n" ::: "memory");
            __syncthreads();
            load_frags(fa, sbase + (uint32_t)((s + 1) % NSTG) * STAGEB, 0);
        }
        mma_all(fb);
    }

    // ---- epilogue: add bias, write force ----
    #pragma unroll
    for (int nt = 0; nt < 4; ++nt) {
        int c = n0 + wn + nt * 8 + (lane & 3) * 2;
        float b0 = __ldg(&bias[c]);
        float b1 = __ldg(&bias[c + 1]);
        #pragma unroll
        for (int mt = 0; mt < 4; ++mt) {
            int r = m0 + wm + mt * 16 + (lane >> 2);
            float2 lo = make_float2(acc[mt][nt][0] + b0, acc[mt][nt][1] + b1);
            float2 hi = make_float2(acc[mt][nt][2] + b0, acc[mt][nt][3] + b1);
            *reinterpret_cast<float2*>(&g_force[(size_t)r * NSZ + c]) = lo;
            *reinterpret_cast<float2*>(&g_force[(size_t)(r + 8) * NSZ + c]) = hi;
        }
    }
}

// ---------------- scan phase A: per-chunk carries (zero init) -------------
__global__ __launch_bounds__(256) void scanA_kernel(const float* __restrict__ freq,
                                                    const float* __restrict__ damp) {
    int c4 = blockIdx.x * 256 + threadIdx.x;
    int j = blockIdx.y;
    int n = c4 * 4;
    float4 f4 = *reinterpret_cast<const float4*>(freq + n);
    float4 d4 = *reinterpret_cast<const float4*>(damp + n);
    float wx = (TWO_PI * f4.x) * (TWO_PI * f4.x);
    float wy = (TWO_PI * f4.y) * (TWO_PI * f4.y);
    float wz = (TWO_PI * f4.z) * (TWO_PI * f4.z);
    float ww = (TWO_PI * f4.w) * (TWO_PI * f4.w);
    float sx = 0, sy = 0, sz = 0, sw = 0, vx = 0, vy = 0, vz = 0, vw = 0;
    const float4* fp = reinterpret_cast<const float4*>(g_force + (size_t)j * LCH * NSZ + n);
    #pragma unroll 8
    for (int k = 0; k < LCH; ++k) {
        float4 fr = fp[(size_t)k * (NSZ / 4)];
        float ax = fmaf(-wx, sx, fmaf(-d4.x, vx, fr.x)); vx = fmaf(ax, DT, vx); sx = fmaf(vx, DT, sx);
        float ay = fmaf(-wy, sy, fmaf(-d4.y, vy, fr.y)); vy = fmaf(ay, DT, vy); sy = fmaf(vy, DT, sy);
        float az = fmaf(-wz, sz, fmaf(-d4.z, vz, fr.z)); vz = fmaf(az, DT, vz); sz = fmaf(vz, DT, sz);
        float aw = fmaf(-ww, sw, fmaf(-d4.w, vw, fr.w)); vw = fmaf(aw, DT, vw); sw = fmaf(vw, DT, sw);
    }
    *reinterpret_cast<float4*>(g_cs + (size_t)j * NSZ + n) = make_float4(sx, sy, sz, sw);
    *reinterpret_cast<float4*>(g_cv + (size_t)j * NSZ + n) = make_float4(vx, vy, vz, vw);
}

// ---------------- combine: z_{j+1} = M^L z_j + carry_j --------------------
__global__ __launch_bounds__(256) void combine_kernel(const float* __restrict__ freq,
                                                      const float* __restrict__ damp) {
    int n = blockIdx.x * 256 + threadIdx.x;
    float f = freq[n], dmp = damp[n];
    float w2 = (TWO_PI * f) * (TWO_PI * f);
    float b00 = 1.0f - w2 * DT * DT;
    float b01 = DT * (1.0f - dmp * DT);
    float b10 = -w2 * DT;
    float b11 = 1.0f - dmp * DT;
    float e00 = 1.0f, e01 = 0.0f, e10 = 0.0f, e11 = 1.0f;
    int p = LCH;
    while (p) {
        if (p & 1) {
            float t00 = b00 * e00 + b01 * e10, t01 = b00 * e01 + b01 * e11;
            float t10 = b10 * e00 + b11 * e10, t11 = b10 * e01 + b11 * e11;
            e00 = t00; e01 = t01; e10 = t10; e11 = t11;
        }
        float s00 = b00 * b00 + b01 * b10, s01 = b00 * b01 + b01 * b11;
        float s10 = b10 * b00 + b11 * b10, s11 = b10 * b01 + b11 * b11;
        b00 = s00; b01 = s01; b10 = s10; b11 = s11;
        p >>= 1;
    }
    float sz = 0.0f, vz = 0.0f;
    for (int j = 0; j < CCH; ++j) {
        g_zs[j * NSZ + n] = sz;
        g_zv[j * NSZ + n] = vz;
        float cs = g_cs[j * NSZ + n], cv = g_cv[j * NSZ + n];
        float ns = e00 * sz + e01 * vz + cs;
        float nv = e10 * sz + e11 * vz + cv;
        sz = ns; vz = nv;
    }
}

// ---------------- scan phase B: full scan from z, + osc, clip, write ------
__global__ __launch_bounds__(256) void scanB_kernel(const float* __restrict__ freq,
                                                    const float* __restrict__ damp,
                                                    const float* __restrict__ amp,
                                                    const float* __restrict__ phase,
                                                    float* __restrict__ out) {
    int c4 = blockIdx.x * 256 + threadIdx.x;
    int j = blockIdx.y;
    int n = c4 * 4;
    float4 f4 = *reinterpret_cast<const float4*>(freq + n);
    float4 d4 = *reinterpret_cast<const float4*>(damp + n);
    float4 a4 = *reinterpret_cast<const float4*>(amp + n);
    float4 p4 = *reinterpret_cast<const float4*>(phase + n);
    float wx = (TWO_PI * f4.x) * (TWO_PI * f4.x);
    float wy = (TWO_PI * f4.y) * (TWO_PI * f4.y);
    float wz = (TWO_PI * f4.z) * (TWO_PI * f4.z);
    float ww = (TWO_PI * f4.w) * (TWO_PI * f4.w);
    float ox = a4.x * sinf(fmaf(TWO_PI * f4.x, DT, p4.x));
    float oy = a4.y * sinf(fmaf(TWO_PI * f4.y, DT, p4.y));
    float oz = a4.z * sinf(fmaf(TWO_PI * f4.z, DT, p4.z));
    float ow = a4.w * sinf(fmaf(TWO_PI * f4.w, DT, p4.w));
    float4 zs = *reinterpret_cast<const float4*>(g_zs + (size_t)j * NSZ + n);
    float4 zv = *reinterpret_cast<const float4*>(g_zv + (size_t)j * NSZ + n);
    float sx = zs.x, sy = zs.y, szz = zs.z, sww = zs.w;
    float vx = zv.x, vy = zv.y, vzz = zv.z, vww = zv.w;
    const float4* fp = reinterpret_cast<const float4*>(g_force + (size_t)j * LCH * NSZ + n);
    float4* op = reinterpret_cast<float4*>(out + (size_t)j * LCH * NSZ + n);
    #pragma unroll 8
    for (int k = 0; k < LCH; ++k) {
        float4 fr = fp[(size_t)k * (NSZ / 4)];
        float ax = fmaf(-wx, sx, fmaf(-d4.x, vx, fr.x)); vx = fmaf(ax, DT, vx); sx = fmaf(vx, DT, sx);
        float ay = fmaf(-wy, sy, fmaf(-d4.y, vy, fr.y)); vy = fmaf(ay, DT, vy); sy = fmaf(vy, DT, sy);
        float az = fmaf(-wz, szz, fmaf(-d4.z, vzz, fr.z)); vzz = fmaf(az, DT, vzz); szz = fmaf(vzz, DT, szz);
        float aw = fmaf(-ww, sww, fmaf(-d4.w, vww, fr.w)); vww = fmaf(aw, DT, vww); sww = fmaf(vww, DT, sww);
        float4 o;
        o.x = fminf(1.0f, fmaxf(-1.0f, sx + ox));
        o.y = fminf(1.0f, fmaxf(-1.0f, sy + oy));
        o.z = fminf(1.0f, fmaxf(-1.0f, szz + oz));
        o.w = fminf(1.0f, fmaxf(-1.0f, sww + ow));
        op[(size_t)k * (NSZ / 4)] = o;
    }
}

// ---------------------------------------------------------------------------
extern "C" void kernel_launch(void* const* d_in, const int* in_sizes, int n_in,
                              void* d_out, int out_size)
{
    const float* x     = (const float*)d_in[0];
    const float* W     = (const float*)d_in[1];
    const float* b     = (const float*)d_in[2];
    const float* amp   = (const float*)d_in[3];
    const float* freq  = (const float*)d_in[4];
    const float* phase = (const float*)d_in[5];
    const float* damp  = (const float*)d_in[6];
    float* out = (float*)d_out;
    (void)in_sizes; (void)n_in; (void)out_size;

    static bool attr_done = false;
    if (!attr_done) {
        cudaFuncSetAttribute(gemm_f16_kernel,
                             cudaFuncAttributeMaxDynamicSharedMemorySize, SMEM_BYTES);
        attr_done = true;
    }

    // 1. convert operands to fp16
    cvtA_kernel<<<(BSZ * DSZ / 4) / 256, 256>>>(x);
    cvtW_kernel<<<(NSZ * DSZ / 4) / 256, 256>>>(W);

    // 2. fp16 tensor-core GEMM -> g_force (bias fused in epilogue)
    dim3 ggrid(NSZ / GBN, BSZ / GBM);
    gemm_f16_kernel<<<ggrid, 256, SMEM_BYTES>>>(b);

    // 3. chunked parallel scan
    dim3 sgrid(NSZ / 4 / 256, CCH);
    scanA_kernel<<<sgrid, 256>>>(freq, damp);
    combine_kernel<<<NSZ / 256, 256>>>(freq, damp);
    scanB_kernel<<<sgrid, 256>>>(freq, damp, amp, phase, out);
}